// round 6
// baseline (speedup 1.0000x reference)
#include <cuda_runtime.h>
#include <math.h>
#include <stdint.h>

// Problem constants
#define NB   128      // batch
#define NT   512      // seq len
#define ND   512      // input size
#define NH   1024     // hidden size
#define NG   4096     // packed gate columns
#define NOUT 512      // output size
#define NBLK 128      // persistent grid size (<= 148 SMs, all co-resident)

// K permutation for tf32 fragment vectorization (within 16-wide windows):
//   pi(k) = (k & ~15) | ((k&3)<<2) | ((k>>2)&3)
__device__ __host__ __forceinline__ int kperm(int k) {
    return (k & ~15) | ((k & 3) << 2) | ((k >> 2) & 3);
}

// ---------------- device scratch (static allocations only) ----------------
__device__ float g_Wxt[(size_t)NG * ND];        //  8 MB tf32 [packed n][pi(k)]
__device__ float g_Wht[(size_t)NG * NH];        // 16 MB tf32 [packed n][pi(k)]
__device__ float g_bias[NG];
__device__ float g_xp[(size_t)NT * NB * ND];    // 128 MB tf32 [t*128+b][pi(k)]
__device__ float g_Gx[268435456];               //   1 GB fp32 [t*128+b][packed n]
__device__ float g_h[2][NB * NH];               // h (tf32-valued) at [b][pi(j)]
__device__ float g_c[NB * NH];                  // final c at [b][pi(j)]
__device__ float g_hlin[NB * NH];
__device__ float g_clin[NB * NH];
__device__ volatile unsigned g_bar;             // grid barrier counter

__device__ __forceinline__ uint32_t f2tf32(float f) {
    uint32_t r;
    asm("cvt.rna.tf32.f32 %0, %1;" : "=r"(r) : "f"(f));
    return r;
}

__device__ __forceinline__ void mma_tf32(float4& d,
                                         uint32_t a0, uint32_t a1, uint32_t a2, uint32_t a3,
                                         uint32_t b0, uint32_t b1) {
    asm volatile(
        "mma.sync.aligned.m16n8k8.row.col.f32.tf32.tf32.f32 "
        "{%0,%1,%2,%3},{%4,%5,%6,%7},{%8,%9},{%0,%1,%2,%3};"
        : "+f"(d.x), "+f"(d.y), "+f"(d.z), "+f"(d.w)
        : "r"(a0), "r"(a1), "r"(a2), "r"(a3), "r"(b0), "r"(b1));
}

__device__ __forceinline__ float sigf(float v) { return 1.f / (1.f + expf(-v)); }

// ---------------------------------------------------------------------------
// Pack weights. Gate-pair column packing within each 16-col group:
//   unit j: g16=j>>2, u=j&3: col(i)=g16*16+2u, col(f)=+1, col(o)=g16*16+8+2u, col(c~)=+9
// Both Wx and Wh stored transposed [packed n][pi(k)] as tf32 bits.
// ---------------------------------------------------------------------------
__global__ void pack_kernel(const float* __restrict__ Wi, const float* __restrict__ Wf,
                            const float* __restrict__ Wo, const float* __restrict__ Wc,
                            const float* __restrict__ bi, const float* __restrict__ bf,
                            const float* __restrict__ bo, const float* __restrict__ bc) {
    int idx = blockIdx.x * blockDim.x + threadIdx.x;
    if (idx < 1536 * NH) {
        int k = idx >> 10;          // row in [0,1536)
        int j = idx & 1023;         // hidden unit
        int g16 = j >> 2, u = j & 3;
        int ci = g16 * 16 + 2 * u;
        int cf = ci + 1;
        int co = g16 * 16 + 8 + 2 * u;
        int cc = co + 1;
        float vi = Wi[idx], vf = Wf[idx], vo = Wo[idx], vc = Wc[idx];
        if (k < ND) {
            int pk = kperm(k);
            g_Wxt[(size_t)ci * ND + pk] = __uint_as_float(f2tf32(vi));
            g_Wxt[(size_t)cf * ND + pk] = __uint_as_float(f2tf32(vf));
            g_Wxt[(size_t)co * ND + pk] = __uint_as_float(f2tf32(vo));
            g_Wxt[(size_t)cc * ND + pk] = __uint_as_float(f2tf32(vc));
        } else {
            int pk = kperm(k - ND);
            g_Wht[(size_t)ci * NH + pk] = __uint_as_float(f2tf32(vi));
            g_Wht[(size_t)cf * NH + pk] = __uint_as_float(f2tf32(vf));
            g_Wht[(size_t)co * NH + pk] = __uint_as_float(f2tf32(vo));
            g_Wht[(size_t)cc * NH + pk] = __uint_as_float(f2tf32(vc));
        }
    }
    if (idx < NH) {
        int g16 = idx >> 2, u = idx & 3;
        g_bias[g16 * 16 + 2 * u]         = bi[idx];
        g_bias[g16 * 16 + 2 * u + 1]     = bf[idx];
        g_bias[g16 * 16 + 8 + 2 * u]     = bo[idx];
        g_bias[g16 * 16 + 8 + 2 * u + 1] = bc[idx];
    }
}

__global__ void init_kernel() {
    int i = blockIdx.x * blockDim.x + threadIdx.x;
    if (i < NB * NH) {
        g_h[0][i] = 0.f;
        g_h[1][i] = 0.f;
    }
    if (i == 0) g_bar = 0u;
}

// x reindex [b][t][d] -> [t*128+b][pi(d)] as tf32 bits
__global__ void xprep_kernel(const float* __restrict__ x) {
    size_t i = (size_t)blockIdx.x * 256 + threadIdx.x;   // 33.55M threads
    int m = (int)(i >> 9), k = (int)(i & 511);
    int b = m & 127, t = m >> 7;
    float v = x[((size_t)b * NT + t) * ND + k];
    g_xp[(size_t)m * ND + kperm(k)] = __uint_as_float(f2tf32(v));
}

// ---------------------------------------------------------------------------
// Gx = X @ Wx + bias via tf32 MMA. M=65536, N=4096, K=512.
// Block tile 128x64, 256 thr, 8 warps = 4(M32) x 2(N32); warp = 2mf x 4nf m16n8k8.
// ---------------------------------------------------------------------------
__global__ void __launch_bounds__(256) gx_kernel() {
    extern __shared__ uint32_t smg[];
    uint32_t (*Asx)[80] = (uint32_t(*)[80])smg;               // [128][80]
    uint32_t (*Bsx)[80] = (uint32_t(*)[80])(smg + 128 * 80);  // [64][80]

    const int tid  = threadIdx.x;
    const int lane = tid & 31, warp = tid >> 5;
    const int wm   = warp >> 1, wn = warp & 1;
    const int gid  = lane >> 2, tig = lane & 3;
    const size_t m0 = (size_t)blockIdx.y * 128;
    const int n0   = blockIdx.x * 64;

    // A stager: 128 rows x 64 k, thread: row=tid>>1, half=tid&1, 32 words
    const int arow = tid >> 1, ah = tid & 1;
    const int axor = (4 * ah) ^ ((arow & 2) << 2);
    const float* pa = g_xp + (m0 + arow) * ND + 32 * ah;
    // B stager: 64 rows x 64 k, thread: row=tid>>2, quarter=tid&3, 16 words
    const int brow = tid >> 2, bq = tid & 3;
    const int bxor = 4 * bq;
    const float* pb = g_Wxt + (size_t)(n0 + brow) * ND + 16 * bq;

    float4 acc[2][4];
#pragma unroll
    for (int mf = 0; mf < 2; mf++)
#pragma unroll
        for (int nf = 0; nf < 4; nf++) acc[mf][nf] = make_float4(0.f, 0.f, 0.f, 0.f);

    float4 ra[8], rb[4];
#pragma unroll
    for (int i = 0; i < 8; i++) ra[i] = *(const float4*)(pa + 4 * i);
#pragma unroll
    for (int i = 0; i < 4; i++) rb[i] = *(const float4*)(pb + 4 * i);

    for (int kt = 0; kt < ND; kt += 64) {
        __syncthreads();
#pragma unroll
        for (int i = 0; i < 8; i++) {
            int col = (32 * ah + 4 * i) ^ axor;
            *(float4*)&Asx[arow][col] = ra[i];
        }
#pragma unroll
        for (int i = 0; i < 4; i++) {
            int col = (16 * bq + 4 * i) ^ bxor;
            *(float4*)&Bsx[brow][col] = rb[i];
        }
        __syncthreads();
        if (kt + 64 < ND) {
#pragma unroll
            for (int i = 0; i < 8; i++) ra[i] = *(const float4*)(pa + kt + 64 + 4 * i);
#pragma unroll
            for (int i = 0; i < 4; i++) rb[i] = *(const float4*)(pb + kt + 64 + 4 * i);
        }
#pragma unroll
        for (int w = 0; w < 4; w++) {
            const int kc   = w * 16 + tig * 4;
            const int colA = kc ^ (4 * (w >> 1));
            const int colB = kc ^ (4 * w);
            uint4 vb[4];
#pragma unroll
            for (int nf = 0; nf < 4; nf++)
                vb[nf] = *(const uint4*)&Bsx[wn * 32 + nf * 8 + gid][colB];
#pragma unroll
            for (int mf = 0; mf < 2; mf++) {
                int R  = wm * 32 + mf * 16 + gid;
                int rx = (R & 2) << 2;
                uint4 va0 = *(const uint4*)&Asx[R][colA ^ rx];
                uint4 va1 = *(const uint4*)&Asx[R + 8][colA ^ rx];
#pragma unroll
                for (int nf = 0; nf < 4; nf++) {
                    mma_tf32(acc[mf][nf], va0.x, va1.x, va0.y, va1.y, vb[nf].x, vb[nf].y);
                    mma_tf32(acc[mf][nf], va0.z, va1.z, va0.w, va1.w, vb[nf].z, vb[nf].w);
                }
            }
        }
    }

#pragma unroll
    for (int mf = 0; mf < 2; mf++)
#pragma unroll
        for (int nf = 0; nf < 4; nf++) {
            int R   = wm * 32 + mf * 16 + gid;
            int col = n0 + wn * 32 + nf * 8 + 2 * tig;
            float b0 = g_bias[col], b1 = g_bias[col + 1];
            float4 a = acc[mf][nf];
            *(float2*)&g_Gx[(m0 + R) * NG + col]     = make_float2(a.x + b0, a.y + b1);
            *(float2*)&g_Gx[(m0 + R + 8) * NG + col] = make_float2(a.z + b0, a.w + b1);
        }
}

// ---------------------------------------------------------------------------
// Persistent LSTM recurrence. grid = 128 blocks (all resident), 256 threads.
// Each block owns 32 gate columns (8 hidden units); its Wh slice lives in
// smem for all 512 steps. c lives in registers. Grid barrier between steps.
// Warp layout: 8 warps = 4(M32) x 2(N16); warp = 2mf x 2nf m16n8k8 frags.
// ---------------------------------------------------------------------------
__global__ void __launch_bounds__(256, 1) lstm_persist() {
    extern __shared__ uint32_t sm[];
    uint32_t (*Wr)[1040] = (uint32_t(*)[1040])sm;              // [32][1040]
    uint32_t (*As)[80]   = (uint32_t(*)[80])(sm + 32 * 1040);  // [128][80]

    const int tid  = threadIdx.x;
    const int lane = tid & 31, warp = tid >> 5;
    const int wm   = warp >> 1, wn = warp & 1;
    const int gid  = lane >> 2, tig = lane & 3;
    const int n0   = blockIdx.x * 32;

    // one-time: load this block's Wh slice into smem (plain layout)
    for (int idx = tid * 4; idx < 32 * 1024; idx += 256 * 4) {
        int r = idx >> 10, c = idx & 1023;
        *(uint4*)&Wr[r][c] = *(const uint4*)&g_Wht[(size_t)(n0 + r) * NH + c];
    }

    // cell state in registers: [mf][row-half]
    float cc[2][2] = {{0.f, 0.f}, {0.f, 0.f}};

    const int j  = blockIdx.x * 8 + wn * 4 + tig;   // hidden unit owned
    const int pj = kperm(j);

    // h stager ids
    const int lrow = tid >> 1, ah = tid & 1;
    const int axor = (4 * ah) ^ ((lrow & 2) << 2);

    __syncthreads();   // Wr ready

    for (int t = 0; t < NT; t++) {
        const float* __restrict__ h_in  = g_h[t & 1];
        float*       __restrict__ h_out = g_h[(t + 1) & 1];
        const float* __restrict__ Gxt   = g_Gx + (size_t)t * NB * NG;

        // prefetch Gx fragments (consumed only at epilogue — latency hidden)
        float2 gx[2][2][2];
#pragma unroll
        for (int mf = 0; mf < 2; mf++)
#pragma unroll
            for (int nf = 0; nf < 2; nf++) {
                int R    = wm * 32 + mf * 16 + gid;
                int ncol = n0 + wn * 16 + nf * 8 + 2 * tig;
                gx[mf][nf][0] = *(const float2*)&Gxt[(size_t)R * NG + ncol];
                gx[mf][nf][1] = *(const float2*)&Gxt[(size_t)(R + 8) * NG + ncol];
            }

        float4 acc[2][2];
#pragma unroll
        for (int mf = 0; mf < 2; mf++)
#pragma unroll
            for (int nf = 0; nf < 2; nf++) acc[mf][nf] = make_float4(0.f, 0.f, 0.f, 0.f);

        const float* pa = h_in + (size_t)lrow * NH + 32 * ah;
        float4 ra[8];
#pragma unroll
        for (int i = 0; i < 8; i++) ra[i] = *(const float4*)(pa + 4 * i);

        for (int kt = 0; kt < NH; kt += 64) {
            __syncthreads();
#pragma unroll
            for (int i = 0; i < 8; i++) {
                int col = (32 * ah + 4 * i) ^ axor;
                *(float4*)&As[lrow][col] = ra[i];   // h already tf32-valued
            }
            __syncthreads();
            if (kt + 64 < NH) {
#pragma unroll
                for (int i = 0; i < 8; i++) ra[i] = *(const float4*)(pa + kt + 64 + 4 * i);
            }
#pragma unroll
            for (int w = 0; w < 4; w++) {
                const int kc   = w * 16 + tig * 4;
                const int colA = kc ^ (4 * (w >> 1));
                uint4 vb0 = *(const uint4*)&Wr[wn * 16 + gid][kt + kc];
                uint4 vb1 = *(const uint4*)&Wr[wn * 16 + 8 + gid][kt + kc];
#pragma unroll
                for (int mf = 0; mf < 2; mf++) {
                    int R  = wm * 32 + mf * 16 + gid;
                    int rx = (R & 2) << 2;
                    uint4 va0 = *(const uint4*)&As[R][colA ^ rx];
                    uint4 va1 = *(const uint4*)&As[R + 8][colA ^ rx];
                    mma_tf32(acc[mf][0], va0.x, va1.x, va0.y, va1.y, vb0.x, vb0.y);
                    mma_tf32(acc[mf][0], va0.z, va1.z, va0.w, va1.w, vb0.z, vb0.w);
                    mma_tf32(acc[mf][1], va0.x, va1.x, va0.y, va1.y, vb1.x, vb1.y);
                    mma_tf32(acc[mf][1], va0.z, va1.z, va0.w, va1.w, vb1.z, vb1.w);
                }
            }
        }

        // epilogue: gates + state update; h stored as tf32-valued float
#pragma unroll
        for (int mf = 0; mf < 2; mf++) {
            int R0 = wm * 32 + mf * 16 + gid;
            {
                float ig = sigf(acc[mf][0].x + gx[mf][0][0].x);
                float fg = sigf(acc[mf][0].y + gx[mf][0][0].y);
                float og = sigf(acc[mf][1].x + gx[mf][1][0].x);
                float ct = tanhf(acc[mf][1].y + gx[mf][1][0].y);
                float c  = fg * cc[mf][0] + ig * ct;
                cc[mf][0] = c;
                h_out[(size_t)R0 * NH + pj] =
                    __uint_as_float(f2tf32(og * tanhf(c)));
            }
            {
                float ig = sigf(acc[mf][0].z + gx[mf][0][1].x);
                float fg = sigf(acc[mf][0].w + gx[mf][0][1].y);
                float og = sigf(acc[mf][1].z + gx[mf][1][1].x);
                float ct = tanhf(acc[mf][1].w + gx[mf][1][1].y);
                float c  = fg * cc[mf][1] + ig * ct;
                cc[mf][1] = c;
                h_out[(size_t)(R0 + 8) * NH + pj] =
                    __uint_as_float(f2tf32(og * tanhf(c)));
            }
        }

        // grid barrier (monotonic counter; all 128 blocks resident)
        __threadfence();
        __syncthreads();
        if (tid == 0) {
            atomicAdd((unsigned*)&g_bar, 1u);
            unsigned target = (unsigned)NBLK * (unsigned)(t + 1);
            while (g_bar < target) { }
        }
        __syncthreads();
        __threadfence();
    }

    // write final c
#pragma unroll
    for (int mf = 0; mf < 2; mf++) {
        int R0 = wm * 32 + mf * 16 + gid;
        g_c[(size_t)R0 * NH + pj]       = cc[mf][0];
        g_c[(size_t)(R0 + 8) * NH + pj] = cc[mf][1];
    }
}

// Un-permute h and c into linear [b][j] layout.
__global__ void unperm_kernel() {
    int i = blockIdx.x * blockDim.x + threadIdx.x;
    if (i < NB * NH) {
        int b = i >> 10, j = i & 1023;
        int pj = kperm(j);
        g_hlin[i] = g_h[0][b * NH + pj];
        g_clin[i] = g_c[b * NH + pj];
    }
}

// ---------------------------------------------------------------------------
// Output projection: out = [h, c] @ W_out + b_out   (M=128, K=2048, N=512)
// ---------------------------------------------------------------------------
__global__ void __launch_bounds__(128) out_kernel(const float* __restrict__ Wout,
                                                  const float* __restrict__ bout,
                                                  float* __restrict__ out) {
    __shared__ float As[8][64];
    __shared__ float Bs[8][64];

    const int tid = threadIdx.x;
    const int tx  = tid & 15;
    const int ty  = tid >> 4;
    const int n0  = blockIdx.x * 64;
    const int m0  = blockIdx.y * 64;

    const int arow  = tid >> 1;
    const int ahalf = (tid & 1) * 4;
    const int bkk   = tid >> 4;
    const int bnn   = (tid & 15) * 4;

    float4 acc[8];
#pragma unroll
    for (int r = 0; r < 8; r++) acc[r] = make_float4(0.f, 0.f, 0.f, 0.f);

    for (int kt = 0; kt < 2 * NH; kt += 8) {
        int k = kt + ahalf;
        const float* asrc = (k < NH)
            ? &g_hlin[(size_t)(m0 + arow) * NH + k]
            : &g_clin[(size_t)(m0 + arow) * NH + (k - NH)];
        float4 av = *(const float4*)asrc;
        float4 bv = *(const float4*)(&Wout[(size_t)(kt + bkk) * NOUT + n0 + bnn]);
        __syncthreads();
        As[ahalf + 0][arow] = av.x;
        As[ahalf + 1][arow] = av.y;
        As[ahalf + 2][arow] = av.z;
        As[ahalf + 3][arow] = av.w;
        *(float4*)&Bs[bkk][bnn] = bv;
        __syncthreads();
#pragma unroll
        for (int k2 = 0; k2 < 8; k2++) {
            float4 b = *(const float4*)&Bs[k2][tx * 4];
            float a[8];
            *(float4*)&a[0] = *(const float4*)&As[k2][ty * 8];
            *(float4*)&a[4] = *(const float4*)&As[k2][ty * 8 + 4];
#pragma unroll
            for (int r = 0; r < 8; r++) {
                acc[r].x += a[r] * b.x;
                acc[r].y += a[r] * b.y;
                acc[r].z += a[r] * b.z;
                acc[r].w += a[r] * b.w;
            }
        }
    }

#pragma unroll
    for (int r = 0; r < 8; r++) {
        int bb = m0 + ty * 8 + r;
        int nn = n0 + tx * 4;
        float4 o = acc[r];
        o.x += bout[nn + 0];
        o.y += bout[nn + 1];
        o.z += bout[nn + 2];
        o.w += bout[nn + 3];
        *(float4*)&out[(size_t)bb * NOUT + nn] = o;
    }
}

__global__ void copyh_kernel(float* __restrict__ out) {
    int i = blockIdx.x * blockDim.x + threadIdx.x;
    if (i < NB * NH) out[NB * NOUT + i] = g_hlin[i];
}

// ---------------------------------------------------------------------------
extern "C" void kernel_launch(void* const* d_in, const int* in_sizes, int n_in,
                              void* d_out, int out_size) {
    const float* x    = (const float*)d_in[0];
    const float* Wi   = (const float*)d_in[1];
    const float* bi   = (const float*)d_in[2];
    const float* Wf   = (const float*)d_in[3];
    const float* bf   = (const float*)d_in[4];
    const float* Wo   = (const float*)d_in[5];
    const float* bo   = (const float*)d_in[6];
    const float* Wc   = (const float*)d_in[7];
    const float* bc   = (const float*)d_in[8];
    const float* Wout = (const float*)d_in[9];
    const float* bout = (const float*)d_in[10];
    float* out = (float*)d_out;

    const int SMEM_GX      = (128 * 80 + 64 * 80) * 4;      // 61.4 KB
    const int SMEM_PERSIST = (32 * 1040 + 128 * 80) * 4;    // 174.1 KB
    cudaFuncSetAttribute(gx_kernel, cudaFuncAttributeMaxDynamicSharedMemorySize, SMEM_GX);
    cudaFuncSetAttribute(lstm_persist, cudaFuncAttributeMaxDynamicSharedMemorySize, SMEM_PERSIST);

    pack_kernel<<<(1536 * NH + 255) / 256, 256>>>(Wi, Wf, Wo, Wc, bi, bf, bo, bc);
    init_kernel<<<(NB * NH + 255) / 256, 256>>>();
    xprep_kernel<<<(NT * NB * ND) / 256, 256>>>(x);
    gx_kernel<<<dim3(NG / 64, (NT * NB) / 128), 256, SMEM_GX>>>();
    lstm_persist<<<NBLK, 256, SMEM_PERSIST>>>();
    unperm_kernel<<<(NB * NH + 255) / 256, 256>>>();
    out_kernel<<<dim3(NOUT / 64, NB / 64), 128>>>(Wout, bout, out);
    copyh_kernel<<<(NB * NH + 255) / 256, 256>>>(out);
}